// round 9
// baseline (speedup 1.0000x reference)
#include <cuda_runtime.h>
#include <cuda_bf16.h>
#include <math.h>

// ---------------------------------------------------------------------------
// Problem constants
// ---------------------------------------------------------------------------
#define Bsz   4
#define Dd    8
#define Ll    512
#define Hh    768
#define Ff    4096
#define NHEAD 8
#define HD    96         // head dim
#define TOPK  64
#define ROWS  16384      // B*D*L rows of H
#define NTOT  12582912LL // 16384*768
#define RES_ROWS 14336   // B*(D-1)*L
#define RES_TOT  11010048LL  // 14336*768
#define Z_TOT    58720256LL  // 14336*4096

#define O_LOSS  0LL
#define O_XHAT  1LL
#define O_NOVEL 11010049LL   // 1 + 11010048
#define O_Z     22020097LL   // 1 + 2*11010048

#define SQRT_HD 9.79795897113271239f   // fp32(sqrt(96)), == sqrtf(96.0f)

// ---------------------------------------------------------------------------
// Static device workspace (allocation-free rule: __device__ globals)
// ---------------------------------------------------------------------------
__device__ float g_ln  [NTOT];
__device__ float g_q   [NTOT];
__device__ float g_k   [NTOT];
__device__ float g_v   [NTOT];
__device__ float g_attn[NTOT];
__device__ float g_x   [NTOT];
__device__ float g_xt  [NTOT];
__device__ float g_sc  [67108864];    // 256 * 512 * 512 scores
__device__ float g_res [RES_TOT];
__device__ float g_z   [Z_TOT];
__device__ float g_dictT[Ff * Hh];
__device__ int   g_tki [RES_ROWS * TOPK];
__device__ float g_tkv [RES_ROWS * TOPK];
__device__ float g_part[3 * RES_ROWS]; // pred | recon | sparse partials

// ---------------------------------------------------------------------------
// LayerNorm: one block per row of 768, 256 threads. Two-pass variance
// (reference's literal mean(square(x - mu))), libdevice rsqrtf (matches
// XLA's rsqrt lowering), IEEE divisions, NO fma contraction in the epilogue
// (XLA emits separate mul/add HLO ops).
// ---------------------------------------------------------------------------
__global__ void ln_kernel(const float* __restrict__ x, float* __restrict__ y,
                          const float* __restrict__ gg, const float* __restrict__ bb)
{
    long long row = blockIdx.x;
    const float* xr = x + row * Hh;
    float* yr = y + row * Hh;
    int t = threadIdx.x;
    float v0 = xr[t], v1 = xr[t + 256], v2 = xr[t + 512];
    __shared__ float sa[8], sq[8];

    float s = __fadd_rn(__fadd_rn(v0, v1), v2);
    #pragma unroll
    for (int o = 16; o; o >>= 1) s += __shfl_xor_sync(0xffffffffu, s, o);
    if ((t & 31) == 0) sa[t >> 5] = s;
    __syncthreads();
    s = 0.f;
    #pragma unroll
    for (int w = 0; w < 8; w++) s += sa[w];
    float mu = __fdiv_rn(s, 768.0f);

    float d0 = __fsub_rn(v0, mu), d1 = __fsub_rn(v1, mu), d2 = __fsub_rn(v2, mu);
    float s2 = __fadd_rn(__fadd_rn(__fmul_rn(d0, d0), __fmul_rn(d1, d1)), __fmul_rn(d2, d2));
    #pragma unroll
    for (int o = 16; o; o >>= 1) s2 += __shfl_xor_sync(0xffffffffu, s2, o);
    if ((t & 31) == 0) sq[t >> 5] = s2;
    __syncthreads();
    s2 = 0.f;
    #pragma unroll
    for (int w = 0; w < 8; w++) s2 += sq[w];
    float var  = __fdiv_rn(s2, 768.0f);
    float rstd = rsqrtf(__fadd_rn(var, 1e-5f));

    yr[t]       = __fadd_rn(__fmul_rn(__fmul_rn(d0, rstd), gg[t]),       bb[t]);
    yr[t + 256] = __fadd_rn(__fmul_rn(__fmul_rn(d1, rstd), gg[t + 256]), bb[t + 256]);
    yr[t + 512] = __fadd_rn(__fmul_rn(__fmul_rn(d2, rstd), gg[t + 512]), bb[t + 512]);
}

// ---------------------------------------------------------------------------
// Generic tiled SGEMM, STRICT k-ascending fp32 FMA accumulation per output
// element (bit-path matches cuBLAS / Eigen k-loops — this correlation with
// the reference's rounding is what protects the top-k boundary; do NOT
// "improve" the accumulation).
//   TRANSB=true : C[M,N] = A[M,K] * B[N,K]^T
//   TRANSB=false: C[M,N] = A[M,K] * B[K,N]
// BM=128, BN=64, BK=16, 256 threads, 8x4 register tile. Two-level batch
// strides. Optional add-source, bias, relu.
// ---------------------------------------------------------------------------
template<bool TRANSB>
__global__ void sgemm_kernel(const float* __restrict__ Ag, const float* __restrict__ Bg,
                             float* __restrict__ Cg,
                             const float* __restrict__ addsrc, const float* __restrict__ bias,
                             int M, int N, int K, int lda, int ldb, int ldc,
                             long long sA1, long long sA2, long long sB1, long long sB2,
                             long long sC1, long long sC2, int bdiv,
                             int relu)
{
    int z  = blockIdx.z;
    int z1 = z / bdiv, z2 = z - z1 * bdiv;
    const float* A = Ag + z1 * sA1 + z2 * sA2;
    const float* B = Bg + z1 * sB1 + z2 * sB2;
    float*       C = Cg + z1 * sC1 + z2 * sC2;
    const float* add = addsrc ? (addsrc + z1 * sC1 + z2 * sC2) : (const float*)0;

    __shared__ float As[16][128];
    __shared__ float Bs[16][64];

    int m0 = blockIdx.y * 128;
    int n0 = blockIdx.x * 64;
    int t  = threadIdx.x;
    int tx = t & 15, ty = t >> 4;

    float acc[8][4];
    #pragma unroll
    for (int i = 0; i < 8; i++)
        #pragma unroll
        for (int j = 0; j < 4; j++) acc[i][j] = 0.f;

    for (int k0 = 0; k0 < K; k0 += 16) {
        #pragma unroll
        for (int r = 0; r < 2; r++) {
            int i   = t + r * 256;
            int row = i >> 2, kq = i & 3;
            float4 a4 = *(const float4*)(A + (long long)(m0 + row) * lda + (k0 + kq * 4));
            As[kq*4+0][row] = a4.x;
            As[kq*4+1][row] = a4.y;
            As[kq*4+2][row] = a4.z;
            As[kq*4+3][row] = a4.w;
        }
        if (TRANSB) {
            int n = t >> 2, kq = t & 3;
            float4 b4 = make_float4(0.f, 0.f, 0.f, 0.f);
            if (n0 + n < N)
                b4 = *(const float4*)(B + (long long)(n0 + n) * ldb + (k0 + kq * 4));
            Bs[kq*4+0][n] = b4.x;
            Bs[kq*4+1][n] = b4.y;
            Bs[kq*4+2][n] = b4.z;
            Bs[kq*4+3][n] = b4.w;
        } else {
            int rk = t >> 4, nq = t & 15;
            float4 b4 = make_float4(0.f, 0.f, 0.f, 0.f);
            if (n0 + nq * 4 < N)
                b4 = *(const float4*)(B + (long long)(k0 + rk) * ldb + (n0 + nq * 4));
            *(float4*)&Bs[rk][nq * 4] = b4;
        }
        __syncthreads();
        #pragma unroll
        for (int k = 0; k < 16; k++) {
            float a[8], b[4];
            *(float4*)&a[0] = *(const float4*)&As[k][ty * 8];
            *(float4*)&a[4] = *(const float4*)&As[k][ty * 8 + 4];
            *(float4*)&b[0] = *(const float4*)&Bs[k][tx * 4];
            #pragma unroll
            for (int i = 0; i < 8; i++)
                #pragma unroll
                for (int j = 0; j < 4; j++)
                    acc[i][j] += a[i] * b[j];   // FFMA, strict k order
        }
        __syncthreads();
    }

    int n = n0 + tx * 4;
    if (n < N) {
        #pragma unroll
        for (int i = 0; i < 8; i++) {
            long long m = m0 + ty * 8 + i;
            float4 r;
            r.x = acc[i][0]; r.y = acc[i][1]; r.z = acc[i][2]; r.w = acc[i][3];
            if (bias) {
                r.x = __fadd_rn(r.x, bias[n]);   r.y = __fadd_rn(r.y, bias[n+1]);
                r.z = __fadd_rn(r.z, bias[n+2]); r.w = __fadd_rn(r.w, bias[n+3]);
            }
            if (add) {
                float4 a4 = *(const float4*)(add + m * ldc + n);
                r.x = __fadd_rn(r.x, a4.x); r.y = __fadd_rn(r.y, a4.y);
                r.z = __fadd_rn(r.z, a4.z); r.w = __fadd_rn(r.w, a4.w);
            }
            if (relu) {
                r.x = fmaxf(r.x, 0.f); r.y = fmaxf(r.y, 0.f);
                r.z = fmaxf(r.z, 0.f); r.w = fmaxf(r.w, 0.f);
            }
            *(float4*)(C + m * ldc + n) = r;
        }
    }
}

// ---------------------------------------------------------------------------
// Row softmax over 512 (non-causal), in place. One block (128 thr) per row.
// Scores divided by sqrt(96) with IEEE division (reference divides the score
// tensor), libdevice expf (matches XLA's exp lowering), IEEE normalize.
// ---------------------------------------------------------------------------
__global__ void softmax512_kernel(float* __restrict__ sc)
{
    long long row = blockIdx.x;
    float* p = sc + row * 512;
    int t = threadIdx.x;
    float v[4];
    #pragma unroll
    for (int i = 0; i < 4; i++) v[i] = __fdiv_rn(p[t + i * 128], SQRT_HD);
    float m = fmaxf(fmaxf(v[0], v[1]), fmaxf(v[2], v[3]));
    __shared__ float sm[4], ss[4];
    #pragma unroll
    for (int o = 16; o; o >>= 1) m = fmaxf(m, __shfl_xor_sync(0xffffffffu, m, o));
    if ((t & 31) == 0) sm[t >> 5] = m;
    __syncthreads();
    m = fmaxf(fmaxf(sm[0], sm[1]), fmaxf(sm[2], sm[3]));
    float s = 0.f;
    #pragma unroll
    for (int i = 0; i < 4; i++) { v[i] = expf(__fsub_rn(v[i], m)); s += v[i]; }
    #pragma unroll
    for (int o = 16; o; o >>= 1) s += __shfl_xor_sync(0xffffffffu, s, o);
    if ((t & 31) == 0) ss[t >> 5] = s;
    __syncthreads();
    s = ss[0] + ss[1] + ss[2] + ss[3];
    #pragma unroll
    for (int i = 0; i < 4; i++) p[t + i * 128] = __fdiv_rn(v[i], s);
}

// ---------------------------------------------------------------------------
// Tiny causal attention over depth (D=8 tokens). Block = (bl, head), 128 thr.
// ---------------------------------------------------------------------------
__global__ void attn2_kernel(const float* __restrict__ q, const float* __restrict__ k,
                             const float* __restrict__ v, float* __restrict__ o)
{
    int bl = blockIdx.x;   // 0..2047 = b*512+l
    int h  = blockIdx.y;   // 0..7
    int t  = threadIdx.x;  // 128
    __shared__ float qs[8][97], ks[8][97], vs[8][97], ps[8][8];
    long long base = (long long)bl * 8 * Hh + h * HD;
    if (t < 96) {
        #pragma unroll
        for (int tok = 0; tok < 8; tok++) {
            qs[tok][t] = q[base + tok * Hh + t];
            ks[tok][t] = k[base + tok * Hh + t];
            vs[tok][t] = v[base + tok * Hh + t];
        }
    }
    __syncthreads();
    if (t < 64) {
        int t1 = t >> 3, t2 = t & 7;
        float s = -1e30f;
        if (t2 <= t1) {
            float a = 0.f;
            #pragma unroll 8
            for (int d2 = 0; d2 < 96; d2++) a += qs[t1][d2] * ks[t2][d2];  // FFMA, d ascending
            s = __fdiv_rn(a, SQRT_HD);
        }
        float m = s;
        #pragma unroll
        for (int o2 = 1; o2 <= 4; o2 <<= 1) m = fmaxf(m, __shfl_xor_sync(0xffffffffu, m, o2));
        float e = (t2 <= t1) ? expf(__fsub_rn(s, m)) : 0.0f;
        float sum = e;
        #pragma unroll
        for (int o2 = 1; o2 <= 4; o2 <<= 1) sum += __shfl_xor_sync(0xffffffffu, sum, o2);
        ps[t1][t2] = __fdiv_rn(e, sum);
    }
    __syncthreads();
    if (t < 96) {
        #pragma unroll
        for (int t1 = 0; t1 < 8; t1++) {
            float a = 0.f;
            #pragma unroll
            for (int t2 = 0; t2 < 8; t2++) a += ps[t1][t2] * vs[t2][t];    // FFMA, m ascending
            o[base + t1 * Hh + t] = a;
        }
    }
}

// ---------------------------------------------------------------------------
// Layout permutes: (B,D,L,H) <-> (B,L,D,H)
// ---------------------------------------------------------------------------
__global__ void perm_fwd_kernel(const float* __restrict__ in, float* __restrict__ out)
{
    long long i = (long long)blockIdx.x * 256 + threadIdx.x;
    if (i >= NTOT) return;
    int h = (int)(i % Hh);
    long long r = i / Hh;
    int l = (int)(r % Ll);
    long long bd = r / Ll;
    int dd = (int)(bd % Dd);
    int b  = (int)(bd / Dd);
    out[((long long)(b * Ll + l) * Dd + dd) * Hh + h] = in[i];
}

__global__ void perm_bwd_kernel(const float* __restrict__ in, float* __restrict__ out)
{
    long long i = (long long)blockIdx.x * 256 + threadIdx.x;
    if (i >= NTOT) return;
    int h = (int)(i % Hh);
    long long r = i / Hh;
    int l = (int)(r % Ll);
    long long bd = r / Ll;
    int dd = (int)(bd % Dd);
    int b  = (int)(bd / Dd);
    out[i] = in[((long long)(b * Ll + l) * Dd + dd) * Hh + h];
}

// ---------------------------------------------------------------------------
// Dictionary transpose: (768,4096) -> (4096,768)
// ---------------------------------------------------------------------------
__global__ void transpose_dict_kernel(const float* __restrict__ in, float* __restrict__ out)
{
    __shared__ float tile[32][33];
    int bx = blockIdx.x * 32;   // F dir
    int by = blockIdx.y * 32;   // H dir
    int x = threadIdx.x, y = threadIdx.y;
    #pragma unroll
    for (int j = 0; j < 32; j += 8)
        tile[y + j][x] = in[(long long)(by + y + j) * Ff + bx + x];
    __syncthreads();
    #pragma unroll
    for (int j = 0; j < 32; j += 8)
        out[(long long)(bx + y + j) * Hh + by + x] = tile[x][y + j];
}

// ---------------------------------------------------------------------------
// residual = x[:,1:] - x[:,:-1]  (row-major (B,7,L,H))
// ---------------------------------------------------------------------------
__global__ void res_kernel(const float* __restrict__ x, float* __restrict__ res)
{
    long long i = (long long)blockIdx.x * 256 + threadIdx.x;
    if (i >= RES_TOT) return;
    int h = (int)(i % Hh);
    long long r = i / Hh;
    int l = (int)(r % Ll);
    long long bd = r / Ll;
    int dd = (int)(bd % 7);
    int b  = (int)(bd / 7);
    long long i0 = ((long long)(b * Dd + dd) * Ll + l) * Hh + h;
    res[i] = __fsub_rn(x[i0 + (long long)Ll * Hh], x[i0]);
}

// ---------------------------------------------------------------------------
// Top-64 per row of 4096 (iterative argmax; values relu'd >= 0, ties broken
// by lowest index, matching jax.lax.top_k). Writes z_n directly into d_out,
// records (idx,val) pairs and per-row L1 sum.
// ---------------------------------------------------------------------------
__global__ void topk_kernel(const float* __restrict__ z, float* __restrict__ out,
                            int* __restrict__ tki, float* __restrict__ tkv,
                            float* __restrict__ sparse_part)
{
    long long row = blockIdx.x;
    const float* zr = z + row * Ff;
    __shared__ float rS[Ff];
    __shared__ float wS[Ff];
    __shared__ float bmv[8];
    __shared__ int   bmi[8];
    int t = threadIdx.x;
    for (int i = t; i < Ff; i += 256) { float vv = zr[i]; rS[i] = vv; wS[i] = vv; }
    __syncthreads();

    for (int it = 0; it < TOPK; it++) {
        float bv = -1.0f; int bi = 0x7fffffff;
        for (int i = t; i < Ff; i += 256) {
            float vv = wS[i];
            if (vv > bv || (vv == bv && i < bi)) { bv = vv; bi = i; }
        }
        #pragma unroll
        for (int o = 16; o; o >>= 1) {
            float ov = __shfl_down_sync(0xffffffffu, bv, o);
            int   oi = __shfl_down_sync(0xffffffffu, bi, o);
            if (ov > bv || (ov == bv && oi < bi)) { bv = ov; bi = oi; }
        }
        if ((t & 31) == 0) { bmv[t >> 5] = bv; bmi[t >> 5] = bi; }
        __syncthreads();
        if (t == 0) {
            #pragma unroll
            for (int w = 1; w < 8; w++) {
                if (bmv[w] > bv || (bmv[w] == bv && bmi[w] < bi)) { bv = bmv[w]; bi = bmi[w]; }
            }
            wS[bi] = -1.0f;                 // mark selected
            tki[row * TOPK + it] = bi;
            tkv[row * TOPK + it] = bv;
        }
        __syncthreads();
    }

    // emit full row (selected value or 0) + per-row L1 partial
    float ls = 0.f;
    long long ob = O_Z + row * Ff;
    for (int i = t; i < Ff; i += 256) {
        float vv = (wS[i] < 0.0f) ? rS[i] : 0.0f;
        out[ob + i] = vv;
        ls += vv;
    }
    __shared__ float sp[8];
    #pragma unroll
    for (int o = 16; o; o >>= 1) ls += __shfl_xor_sync(0xffffffffu, ls, o);
    if ((t & 31) == 0) sp[t >> 5] = ls;
    __syncthreads();
    if (t == 0) {
        float s = 0.f;
        #pragma unroll
        for (int w = 0; w < 8; w++) s += sp[w];
        sparse_part[row] = s;
    }
}

// ---------------------------------------------------------------------------
// Sparse decode: x_novel = sum_j z_j * dictT[j], fused with x_hat and
// per-row pred/recon loss partials. Block per row (256 threads, 3 dims each).
// ---------------------------------------------------------------------------
__global__ void novel_kernel(const float* __restrict__ dictT, const float* __restrict__ x,
                             const int* __restrict__ tki, const float* __restrict__ tkv,
                             float* __restrict__ out,
                             float* __restrict__ pred_part, float* __restrict__ recon_part)
{
    long long row = blockIdx.x;     // (b*7+dd)*512 + l
    int t = threadIdx.x;
    __shared__ int   sI[TOPK];
    __shared__ float sV[TOPK];
    if (t < TOPK) { sI[t] = tki[row * TOPK + t]; sV[t] = tkv[row * TOPK + t]; }
    __syncthreads();

    int l = (int)(row % Ll);
    long long bd = row / Ll;
    int dd = (int)(bd % 7);
    int b  = (int)(bd / 7);
    const float* xp = x + ((long long)(b * Dd + dd)     * Ll + l) * Hh;
    const float* xt = x + ((long long)(b * Dd + dd + 1) * Ll + l) * Hh;

    float a0 = 0.f, a1 = 0.f, a2 = 0.f;
    #pragma unroll 4
    for (int j = 0; j < TOPK; j++) {
        float vv = sV[j];
        const float* dr = dictT + (long long)sI[j] * Hh;
        a0 += vv * dr[t];
        a1 += vv * dr[t + 256];
        a2 += vv * dr[t + 512];
    }

    float lr = 0.f, lp = 0.f;
    long long ob = row * Hh;
    float nv[3] = { a0, a1, a2 };
    #pragma unroll
    for (int i = 0; i < 3; i++) {
        int h = t + i * 256;
        float px = xp[h], tg = xt[h];
        float nov = nv[i];
        float xh = __fadd_rn(px, nov);
        out[O_NOVEL + ob + h] = nov;
        out[O_XHAT  + ob + h] = xh;
        float d1 = __fsub_rn(xh, tg); lr += d1 * d1;
        float d2 = __fsub_rn(tg, px); lp += d2 * d2;
    }
    __shared__ float s1[8], s2[8];
    #pragma unroll
    for (int o = 16; o; o >>= 1) {
        lr += __shfl_xor_sync(0xffffffffu, lr, o);
        lp += __shfl_xor_sync(0xffffffffu, lp, o);
    }
    if ((t & 31) == 0) { s1[t >> 5] = lr; s2[t >> 5] = lp; }
    __syncthreads();
    if (t == 0) {
        float r = 0.f, p = 0.f;
        #pragma unroll
        for (int w = 0; w < 8; w++) { r += s1[w]; p += s2[w]; }
        recon_part[row] = r;
        pred_part[row]  = p;
    }
}

// ---------------------------------------------------------------------------
// Final deterministic loss reduction
// ---------------------------------------------------------------------------
__global__ void loss_kernel(const float* __restrict__ pred_part,
                            const float* __restrict__ recon_part,
                            const float* __restrict__ sparse_part,
                            float* __restrict__ out)
{
    int t = threadIdx.x;   // 256
    double sp = 0.0, sr = 0.0, ss = 0.0;
    for (int i = t; i < RES_ROWS; i += 256) {
        sp += (double)pred_part[i];
        sr += (double)recon_part[i];
        ss += (double)sparse_part[i];
    }
    __shared__ double da[256], db[256], dc[256];
    da[t] = sp; db[t] = sr; dc[t] = ss;
    __syncthreads();
    for (int o = 128; o; o >>= 1) {
        if (t < o) { da[t] += da[t + o]; db[t] += db[t + o]; dc[t] += dc[t + o]; }
        __syncthreads();
    }
    if (t == 0) {
        double loss = da[0] / 11010048.0 + db[0] / 11010048.0 + 0.001 * (dc[0] / 58720256.0);
        out[O_LOSS] = (float)loss;
    }
}

// ---------------------------------------------------------------------------
// Host side
// ---------------------------------------------------------------------------
static void sgemm(bool transB, const float* A, const float* B, float* C,
                  const float* add, const float* bias,
                  int M, int N, int K, int lda, int ldb, int ldc,
                  long long sA1, long long sA2, long long sB1, long long sB2,
                  long long sC1, long long sC2, int bdiv, int batch,
                  int relu)
{
    dim3 grid((N + 63) / 64, M / 128, batch);
    if (transB)
        sgemm_kernel<true><<<grid, 256>>>(A, B, C, add, bias, M, N, K, lda, ldb, ldc,
                                          sA1, sA2, sB1, sB2, sC1, sC2, bdiv, relu);
    else
        sgemm_kernel<false><<<grid, 256>>>(A, B, C, add, bias, M, N, K, lda, ldb, ldc,
                                           sA1, sA2, sB1, sB2, sC1, sC2, bdiv, relu);
}

extern "C" void kernel_launch(void* const* d_in, const int* in_sizes, int n_in,
                              void* d_out, int out_size)
{
    const float* zL    = (const float*)d_in[0];
    const float* Wq_l  = (const float*)d_in[1];
    const float* Wk_l  = (const float*)d_in[2];
    const float* Wv_l  = (const float*)d_in[3];
    const float* Wo_l  = (const float*)d_in[4];
    const float* gl    = (const float*)d_in[5];
    const float* bl    = (const float*)d_in[6];
    const float* Wq_d  = (const float*)d_in[7];
    const float* Wk_d  = (const float*)d_in[8];
    const float* Wv_d  = (const float*)d_in[9];
    const float* Wo_d  = (const float*)d_in[10];
    const float* gd    = (const float*)d_in[11];
    const float* bd    = (const float*)d_in[12];
    const float* dict  = (const float*)d_in[13];
    const float* biasn = (const float*)d_in[14];
    float* out = (float*)d_out;

    float *p_ln, *p_q, *p_k, *p_v, *p_attn, *p_x, *p_xt, *p_sc, *p_res, *p_z, *p_dT, *p_tkv, *p_part;
    int *p_tki;
    cudaGetSymbolAddress((void**)&p_ln,   g_ln);
    cudaGetSymbolAddress((void**)&p_q,    g_q);
    cudaGetSymbolAddress((void**)&p_k,    g_k);
    cudaGetSymbolAddress((void**)&p_v,    g_v);
    cudaGetSymbolAddress((void**)&p_attn, g_attn);
    cudaGetSymbolAddress((void**)&p_x,    g_x);
    cudaGetSymbolAddress((void**)&p_xt,   g_xt);
    cudaGetSymbolAddress((void**)&p_sc,   g_sc);
    cudaGetSymbolAddress((void**)&p_res,  g_res);
    cudaGetSymbolAddress((void**)&p_z,    g_z);
    cudaGetSymbolAddress((void**)&p_dT,   g_dictT);
    cudaGetSymbolAddress((void**)&p_tki,  g_tki);
    cudaGetSymbolAddress((void**)&p_tkv,  g_tkv);
    cudaGetSymbolAddress((void**)&p_part, g_part);

    const long long SQH = (long long)Ll * Hh;       // 512*768 seq stride
    const long long SCB = (long long)Ll * Ll;       // 512*512 per-head score size

    // ---------------- Stage A: attention over L (non-causal) ----------------
    ln_kernel<<<ROWS, 256>>>(zL, p_ln, gl, bl);
    sgemm(true, p_ln, Wq_l, p_q, 0, 0, ROWS, Hh, Hh, Hh, Hh, Hh, 0,0,0,0,0,0, 1, 1, 0);
    sgemm(true, p_ln, Wk_l, p_k, 0, 0, ROWS, Hh, Hh, Hh, Hh, Hh, 0,0,0,0,0,0, 1, 1, 0);
    sgemm(true, p_ln, Wv_l, p_v, 0, 0, ROWS, Hh, Hh, Hh, Hh, Hh, 0,0,0,0,0,0, 1, 1, 0);
    // raw scores[seq,head] = Q K^T (scaling done in softmax with IEEE div)
    sgemm(true, p_q, p_k, p_sc, 0, 0, Ll, Ll, HD, Hh, Hh, Ll,
          SQH, HD, SQH, HD, 8*SCB, SCB, NHEAD, 32*NHEAD, 0);
    softmax512_kernel<<<131072, 128>>>(p_sc);
    // attn = P V
    sgemm(false, p_sc, p_v, p_attn, 0, 0, Ll, HD, Ll, Ll, Hh, Hh,
          8*SCB, SCB, SQH, HD, SQH, HD, NHEAD, 32*NHEAD, 0);
    // x = zL + attn Wo^T
    sgemm(true, p_attn, Wo_l, p_x, zL, 0, ROWS, Hh, Hh, Hh, Hh, Hh, 0,0,0,0,0,0, 1, 1, 0);

    // ---------------- Stage B: causal attention over depth D ----------------
    perm_fwd_kernel<<<49152, 256>>>(p_x, p_xt);
    ln_kernel<<<ROWS, 256>>>(p_xt, p_ln, gd, bd);
    sgemm(true, p_ln, Wq_d, p_q, 0, 0, ROWS, Hh, Hh, Hh, Hh, Hh, 0,0,0,0,0,0, 1, 1, 0);
    sgemm(true, p_ln, Wk_d, p_k, 0, 0, ROWS, Hh, Hh, Hh, Hh, Hh, 0,0,0,0,0,0, 1, 1, 0);
    sgemm(true, p_ln, Wv_d, p_v, 0, 0, ROWS, Hh, Hh, Hh, Hh, Hh, 0,0,0,0,0,0, 1, 1, 0);
    attn2_kernel<<<dim3(2048, NHEAD), 128>>>(p_q, p_k, p_v, p_attn);
    sgemm(true, p_attn, Wo_d, p_xt, p_xt, 0, ROWS, Hh, Hh, Hh, Hh, Hh, 0,0,0,0,0,0, 1, 1, 0);
    perm_bwd_kernel<<<49152, 256>>>(p_xt, p_x);

    // ---------------- SAE head ----------------
    transpose_dict_kernel<<<dim3(128, 24), dim3(32, 8)>>>(dict, p_dT);
    res_kernel<<<43008, 256>>>(p_x, p_res);
    // z_dense = relu(res @ dict + bias)   (strict k-seq FMA -> correlates with ref)
    sgemm(false, p_res, dict, p_z, 0, biasn, RES_ROWS, Ff, Hh, Hh, Ff, Ff,
          0,0,0,0,0,0, 1, 1, 1);
    topk_kernel<<<RES_ROWS, 256>>>(p_z, out, p_tki, p_tkv, p_part + 2 * RES_ROWS);
    novel_kernel<<<RES_ROWS, 256>>>(p_dT, p_x, p_tki, p_tkv, out,
                                    p_part, p_part + RES_ROWS);
    loss_kernel<<<1, 256>>>(p_part, p_part + RES_ROWS, p_part + 2 * RES_ROWS, out);
}